// round 1
// baseline (speedup 1.0000x reference)
#include <cuda_runtime.h>
#include <math.h>

// Problem constants (fixed by the dataset)
#define NA      50000
#define NP      10000
#define NE      400000
#define IN_DIM  512
#define FEAT    128
#define NH      8
#define OD      32
#define HD      256   // NH*OD

// ---------------- scratch (static device globals; no allocation) -----------
__device__ float g_z[(size_t)NA * HD];        // 51.2 MB
__device__ float g_ssrc[(size_t)NA * NH];     // 1.6 MB
__device__ float g_eval[(size_t)NE * NH];     // 12.8 MB
__device__ float g_vfeat[NH * FEAT];          // 4 KB
__device__ int   g_counts[NP];
__device__ int   g_offsets[NP];
__device__ int   g_cursor[NP];
__device__ int   g_edge_sorted[NE];

// ---------------- small utility kernels ------------------------------------
__global__ void k_zero_counts() {
    int t = blockIdx.x * blockDim.x + threadIdx.x;
    if (t < NP) g_counts[t] = 0;
}

// v[h][f] = sum_d a_feat[d] * W_feat[(h*OD+d)*FEAT + f],  a_feat = W_attn[64..95]
__global__ void k_vfeat(const float* __restrict__ W_feat,
                        const float* __restrict__ W_attn) {
    int t = blockIdx.x * blockDim.x + threadIdx.x;  // 0..1023
    if (t >= NH * FEAT) return;
    int h = t / FEAT, f = t % FEAT;
    float acc = 0.f;
#pragma unroll
    for (int d = 0; d < OD; ++d)
        acc += W_attn[2 * OD + d] * W_feat[(size_t)(h * OD + d) * FEAT + f];
    g_vfeat[t] = acc;
}

// ---------------- GEMM: z = h @ W_fc^T  (A[M,K] row-major, B[N,K] row-major)
#define BM 128
#define BN 128
#define BK 16
__global__ void __launch_bounds__(256)
k_gemm(const float* __restrict__ A, const float* __restrict__ B,
       float* __restrict__ C, int M) {
    const int K = IN_DIM, N = HD;
    __shared__ float As[BK][BM + 4];
    __shared__ float Bs[BK][BN + 4];
    int bm = blockIdx.y * BM;
    int bn = blockIdx.x * BN;
    int tid = threadIdx.x;
    int tr = tid / 16, tc = tid % 16;   // 16x16 threads, each 8x8 outputs

    float acc[8][8];
#pragma unroll
    for (int i = 0; i < 8; ++i)
#pragma unroll
        for (int j = 0; j < 8; ++j) acc[i][j] = 0.f;

    for (int k0 = 0; k0 < K; k0 += BK) {
#pragma unroll
        for (int it = 0; it < 2; ++it) {
            int idx = tid + it * 256;         // 0..511
            int r = idx >> 2, c4 = (idx & 3) * 4;
            int grow = bm + r;
            float4 v = make_float4(0.f, 0.f, 0.f, 0.f);
            if (grow < M)
                v = *(const float4*)(A + (size_t)grow * K + k0 + c4);
            As[c4 + 0][r] = v.x; As[c4 + 1][r] = v.y;
            As[c4 + 2][r] = v.z; As[c4 + 3][r] = v.w;
            int brow = bn + r;                 // always < N (N=256, BN=128)
            float4 w = *(const float4*)(B + (size_t)brow * K + k0 + c4);
            Bs[c4 + 0][r] = w.x; Bs[c4 + 1][r] = w.y;
            Bs[c4 + 2][r] = w.z; Bs[c4 + 3][r] = w.w;
        }
        __syncthreads();
#pragma unroll
        for (int k = 0; k < BK; ++k) {
            float a[8], b[8];
#pragma unroll
            for (int i = 0; i < 8; ++i) a[i] = As[k][tr * 8 + i];
#pragma unroll
            for (int j = 0; j < 8; ++j) b[j] = Bs[k][tc * 8 + j];
#pragma unroll
            for (int i = 0; i < 8; ++i)
#pragma unroll
                for (int j = 0; j < 8; ++j) acc[i][j] += a[i] * b[j];
        }
        __syncthreads();
    }
#pragma unroll
    for (int i = 0; i < 8; ++i) {
        int grow = bm + tr * 8 + i;
        if (grow < M) {
            float* cp = C + (size_t)grow * N + bn + tc * 8;
#pragma unroll
            for (int j = 0; j < 8; ++j) cp[j] = acc[i][j];
        }
    }
}

// ---------------- s_src[n,h] = z[n,h,:] . a_src ----------------------------
__global__ void k_ssrc(const float* __restrict__ W_attn) {
    int t = blockIdx.x * blockDim.x + threadIdx.x;
    if (t >= NA * NH) return;
    int n = t >> 3, h = t & 7;
    const float* zp = g_z + (size_t)n * HD + h * OD;
    float acc = 0.f;
#pragma unroll
    for (int d = 0; d < OD; ++d) acc += zp[d] * __ldg(&W_attn[d]);
    g_ssrc[t] = acc;
}

// ---------------- edge scores: e_val = leaky_relu(s_src[src] + srl_emb.v^T)
// warp handles 4 edges; 8 lanes per edge, each lane reads 16 floats of the row
__global__ void __launch_bounds__(256) k_eval(const float* __restrict__ srl,
                                              const int* __restrict__ src) {
    __shared__ float sv[NH][FEAT];
    int tid = threadIdx.x;
#pragma unroll
    for (int i = tid; i < NH * FEAT; i += 256)
        ((float*)sv)[i] = g_vfeat[i];
    __syncthreads();

    int warp = tid >> 5, lane = tid & 31;
    int grp = lane >> 3, sl = lane & 7;
    int e = blockIdx.x * 32 + warp * 4 + grp;
    if (e >= NE) return;

    const float4* row = (const float4*)(srl + (size_t)e * FEAT);
    float acc[NH];
#pragma unroll
    for (int h = 0; h < NH; ++h) acc[h] = 0.f;
#pragma unroll
    for (int i = 0; i < 4; ++i) {
        float4 v = row[i * 8 + sl];
        int fb = (i * 8 + sl) * 4;
#pragma unroll
        for (int h = 0; h < NH; ++h) {
            acc[h] += v.x * sv[h][fb + 0];
            acc[h] += v.y * sv[h][fb + 1];
            acc[h] += v.z * sv[h][fb + 2];
            acc[h] += v.w * sv[h][fb + 3];
        }
    }
    float ev = 0.f;
#pragma unroll
    for (int h = 0; h < NH; ++h) {
        float v = acc[h];
        v += __shfl_xor_sync(0xffffffffu, v, 1, 8);
        v += __shfl_xor_sync(0xffffffffu, v, 2, 8);
        v += __shfl_xor_sync(0xffffffffu, v, 4, 8);
        if (h == sl) ev = v;
    }
    int sid = src[e];
    float x = g_ssrc[(size_t)sid * NH + sl] + ev;
    g_eval[(size_t)e * NH + sl] = (x > 0.f) ? x : 0.01f * x;
}

// ---------------- counting sort of edges by dst ----------------------------
__global__ void k_hist(const int* __restrict__ dst) {
    int t = blockIdx.x * blockDim.x + threadIdx.x;
    if (t < NE) atomicAdd(&g_counts[dst[t]], 1);
}

__global__ void __launch_bounds__(1024) k_scan() {
    __shared__ int sh[1024];
    int t = threadIdx.x;
    int base = t * 10;                // 1024*10 >= NP
    int local[10];
    int s = 0;
#pragma unroll
    for (int i = 0; i < 10; ++i) {
        int idx = base + i;
        int c = (idx < NP) ? g_counts[idx] : 0;
        local[i] = s;
        s += c;
    }
    sh[t] = s;
    __syncthreads();
    for (int off = 1; off < 1024; off <<= 1) {
        int v = (t >= off) ? sh[t - off] : 0;
        __syncthreads();
        sh[t] += v;
        __syncthreads();
    }
    int excl = sh[t] - s;             // exclusive prefix of this thread
#pragma unroll
    for (int i = 0; i < 10; ++i) {
        int idx = base + i;
        if (idx < NP) {
            int o = excl + local[i];
            g_offsets[idx] = o;
            g_cursor[idx] = o;
        }
    }
}

__global__ void k_scatter(const int* __restrict__ dst) {
    int t = blockIdx.x * blockDim.x + threadIdx.x;
    if (t < NE) {
        int p = atomicAdd(&g_cursor[dst[t]], 1);
        g_edge_sorted[p] = t;
    }
}

// ---------------- per-segment softmax + weighted gather of z ---------------
// block = one destination; 256 threads: t -> (h = t/32, d = t%32)
__global__ void __launch_bounds__(256) k_segment(const int* __restrict__ src,
                                                 float* __restrict__ out) {
    int p = blockIdx.x;
    int t = threadIdx.x;
    int h = t >> 5;
    int start = g_offsets[p];
    int cnt = g_counts[p];
    float* op = out + (size_t)p * HD + t;
    if (cnt == 0) { *op = 0.f; return; }

    float m = -3.0e38f;
    for (int i = 0; i < cnt; ++i) {
        int eid = g_edge_sorted[start + i];
        m = fmaxf(m, g_eval[(size_t)eid * NH + h]);
    }
    float denom = 0.f, acc = 0.f;
    for (int i = 0; i < cnt; ++i) {
        int eid = g_edge_sorted[start + i];
        float w = expf(g_eval[(size_t)eid * NH + h] - m);
        denom += w;
        int sid = src[eid];
        acc += w * g_z[(size_t)sid * HD + t];
    }
    *op = acc / denom;
}

// ---------------- launcher --------------------------------------------------
extern "C" void kernel_launch(void* const* d_in, const int* in_sizes, int n_in,
                              void* d_out, int out_size) {
    const float* h      = (const float*)d_in[0];
    const float* srl    = (const float*)d_in[1];
    const int*   src    = (const int*)d_in[2];
    const int*   dst    = (const int*)d_in[3];
    const float* W_fc   = (const float*)d_in[4];
    const float* W_feat = (const float*)d_in[5];
    const float* W_attn = (const float*)d_in[6];
    float* out = (float*)d_out;

    // independent prologue
    k_zero_counts<<<(NP + 255) / 256, 256>>>();
    k_vfeat<<<(NH * FEAT + 255) / 256, 256>>>(W_feat, W_attn);

    // z GEMM
    {
        float* zptr;
        cudaGetSymbolAddress((void**)&zptr, g_z);
        dim3 grid(HD / BN, (NA + BM - 1) / BM);
        k_gemm<<<grid, 256>>>(h, W_fc, zptr, NA);
    }

    k_ssrc<<<(NA * NH + 255) / 256, 256>>>(W_attn);
    k_eval<<<(NE + 31) / 32, 256>>>(srl, src);

    k_hist<<<(NE + 255) / 256, 256>>>(dst);
    k_scan<<<1, 1024>>>();
    k_scatter<<<(NE + 255) / 256, 256>>>(dst);

    k_segment<<<NP, 256>>>(src, out);
}

// round 3
// speedup vs baseline: 1.3001x; 1.3001x over previous
#include <cuda_runtime.h>
#include <cstdint>
#include <math.h>

// Problem constants (fixed by the dataset)
#define NA      50000
#define NP      10000
#define NE      400000
#define IN_DIM  512
#define FEAT    128
#define NH      8
#define OD      32
#define HD      256   // NH*OD

// ---------------- scratch (static device globals; no allocation) -----------
__device__ float g_z[(size_t)NA * HD];        // 51.2 MB
__device__ float g_ssrc[(size_t)NA * NH];     // 1.6 MB
__device__ float g_eval[(size_t)NE * NH];     // 12.8 MB
__device__ float g_vfeat[NH * FEAT];          // 4 KB
__device__ int   g_counts[NP];
__device__ int   g_offsets[NP];
__device__ int   g_cursor[NP];
__device__ int   g_edge_sorted[NE];

// ---------------- small utility kernels ------------------------------------
__global__ void k_zero_counts() {
    int t = blockIdx.x * blockDim.x + threadIdx.x;
    if (t < NP) g_counts[t] = 0;
}

// v[h][f] = sum_d a_feat[d] * W_feat[(h*OD+d)*FEAT + f],  a_feat = W_attn[64..95]
__global__ void k_vfeat(const float* __restrict__ W_feat,
                        const float* __restrict__ W_attn) {
    int t = blockIdx.x * blockDim.x + threadIdx.x;
    if (t >= NH * FEAT) return;
    int h = t / FEAT, f = t % FEAT;
    float acc = 0.f;
#pragma unroll
    for (int d = 0; d < OD; ++d)
        acc += W_attn[2 * OD + d] * W_feat[(size_t)(h * OD + d) * FEAT + f];
    g_vfeat[t] = acc;
}

// ====================== 3xTF32 tensor-core GEMM =============================
// C[M,N] = A[M,K] @ B[N,K]^T   (A = h, B = W_fc row-major)
// Block tile 128x128x16, warps 2(m) x 4(n), warp tile 64x32 -> 4x4 mma tiles.
// Each operand split x = hi + lo (tf32);  C += Ah*Bh + Al*Bh + Ah*Bl.
#define GBM 128
#define GBN 128
#define GBK 16
#define APAD 4
#define SROW (GBK + APAD)

__device__ __forceinline__ void cp16(uint32_t dst, const void* src, int srcsize) {
    asm volatile("cp.async.cg.shared.global [%0], [%1], 16, %2;\n"
                 :: "r"(dst), "l"(src), "r"(srcsize));
}

__device__ __forceinline__ void tf32_split(float x, uint32_t& hi, uint32_t& lo) {
    uint32_t h;
    asm("cvt.rna.tf32.f32 %0, %1;" : "=r"(h) : "f"(x));
    hi = h;
    float r = x - __uint_as_float(h);
    uint32_t l;
    asm("cvt.rna.tf32.f32 %0, %1;" : "=r"(l) : "f"(r));
    lo = l;
}

#define MMA_TF32(D, A0, A1, A2, A3, B0, B1)                                   \
    asm volatile(                                                             \
        "mma.sync.aligned.m16n8k8.row.col.f32.tf32.tf32.f32 "                 \
        "{%0,%1,%2,%3}, {%4,%5,%6,%7}, {%8,%9}, {%0,%1,%2,%3};"               \
        : "+f"(D[0]), "+f"(D[1]), "+f"(D[2]), "+f"(D[3])                      \
        : "r"(A0), "r"(A1), "r"(A2), "r"(A3), "r"(B0), "r"(B1))

__global__ void __launch_bounds__(256, 2)
k_gemm_3xtf32(const float* __restrict__ A, const float* __restrict__ B,
              float* __restrict__ C) {
    const int M = NA, K = IN_DIM;
    __shared__ float As[2][GBM][SROW];
    __shared__ float Bs[2][GBN][SROW];

    const int bm = blockIdx.y * GBM;
    const int bn = blockIdx.x * GBN;
    const int tid = threadIdx.x;
    const int warp = tid >> 5, lane = tid & 31;
    const int g = lane >> 2, tg = lane & 3;
    const int wm = (warp >> 2) * 64;
    const int wn = (warp & 3) * 32;

    float acc[4][4][4];
#pragma unroll
    for (int mi = 0; mi < 4; ++mi)
#pragma unroll
        for (int nj = 0; nj < 4; ++nj)
#pragma unroll
            for (int r = 0; r < 4; ++r) acc[mi][nj][r] = 0.f;

    const int r0 = tid >> 2;
    const int c0 = (tid & 3) * 4;
    const int NITER = K / GBK;        // 32

    // prologue: tile 0
    {
#pragma unroll
        for (int it = 0; it < 2; ++it) {
            int r = r0 + it * 64;
            int grow = bm + r;
            uint32_t da = (uint32_t)__cvta_generic_to_shared(&As[0][r][c0]);
            cp16(da, A + (size_t)grow * K + c0, grow < M ? 16 : 0);
            uint32_t db = (uint32_t)__cvta_generic_to_shared(&Bs[0][r][c0]);
            cp16(db, B + (size_t)(bn + r) * K + c0, 16);
        }
        asm volatile("cp.async.commit_group;\n" ::);
    }

    for (int t = 0; t < NITER; ++t) {
        asm volatile("cp.async.wait_group 0;\n" ::);
        __syncthreads();

        if (t + 1 < NITER) {
            int kb = (t + 1) * GBK;
            int nb = (t + 1) & 1;
#pragma unroll
            for (int it = 0; it < 2; ++it) {
                int r = r0 + it * 64;
                int grow = bm + r;
                uint32_t da = (uint32_t)__cvta_generic_to_shared(&As[nb][r][c0]);
                cp16(da, A + (size_t)grow * K + kb + c0, grow < M ? 16 : 0);
                uint32_t db = (uint32_t)__cvta_generic_to_shared(&Bs[nb][r][c0]);
                cp16(db, B + (size_t)(bn + r) * K + kb + c0, 16);
            }
            asm volatile("cp.async.commit_group;\n" ::);
        }

        const int buf = t & 1;
#pragma unroll
        for (int ks = 0; ks < 2; ++ks) {
            const int kk = ks * 8 + tg;
            uint32_t bh[4][2], bl[4][2];
#pragma unroll
            for (int nj = 0; nj < 4; ++nj) {
                const float* bp = &Bs[buf][wn + nj * 8 + g][0];
                tf32_split(bp[kk],     bh[nj][0], bl[nj][0]);
                tf32_split(bp[kk + 4], bh[nj][1], bl[nj][1]);
            }
#pragma unroll
            for (int mi = 0; mi < 4; ++mi) {
                const float* ap = &As[buf][wm + mi * 16 + g][0];
                uint32_t ah[4], al[4];
                tf32_split(ap[kk],                ah[0], al[0]);
                tf32_split(ap[8 * SROW + kk],     ah[1], al[1]);
                tf32_split(ap[kk + 4],            ah[2], al[2]);
                tf32_split(ap[8 * SROW + kk + 4], ah[3], al[3]);
#pragma unroll
                for (int nj = 0; nj < 4; ++nj) {
                    // correction terms first, hi*hi last
                    MMA_TF32(acc[mi][nj], al[0], al[1], al[2], al[3],
                             bh[nj][0], bh[nj][1]);
                    MMA_TF32(acc[mi][nj], ah[0], ah[1], ah[2], ah[3],
                             bl[nj][0], bl[nj][1]);
                    MMA_TF32(acc[mi][nj], ah[0], ah[1], ah[2], ah[3],
                             bh[nj][0], bh[nj][1]);
                }
            }
        }
    }

    // epilogue
#pragma unroll
    for (int mi = 0; mi < 4; ++mi) {
        int row0 = bm + wm + mi * 16 + g;
#pragma unroll
        for (int nj = 0; nj < 4; ++nj) {
            int col = bn + wn + nj * 8 + tg * 2;
            if (row0 < M)
                *(float2*)&C[(size_t)row0 * HD + col] =
                    make_float2(acc[mi][nj][0], acc[mi][nj][1]);
            if (row0 + 8 < M)
                *(float2*)&C[(size_t)(row0 + 8) * HD + col] =
                    make_float2(acc[mi][nj][2], acc[mi][nj][3]);
        }
    }
}

// ---------------- s_src[n,h] = z[n,h,:] . a_src  (warp per node, coalesced) --
__global__ void __launch_bounds__(256) k_ssrc(const float* __restrict__ W_attn) {
    int gw = (blockIdx.x * blockDim.x + threadIdx.x) >> 5;
    int lane = threadIdx.x & 31;
    if (gw >= NA) return;
    const float4* zp = (const float4*)(g_z + (size_t)gw * HD);
    float4 v0 = zp[lane];
    float4 v1 = zp[lane + 32];
    float4 a4 = *(const float4*)(W_attn + (lane & 7) * 4);
    float acc0 = v0.x * a4.x + v0.y * a4.y + v0.z * a4.z + v0.w * a4.w;
    float acc1 = v1.x * a4.x + v1.y * a4.y + v1.z * a4.z + v1.w * a4.w;
#pragma unroll
    for (int off = 1; off < 8; off <<= 1) {
        acc0 += __shfl_xor_sync(0xffffffffu, acc0, off);
        acc1 += __shfl_xor_sync(0xffffffffu, acc1, off);
    }
    if ((lane & 7) == 0) {
        g_ssrc[(size_t)gw * NH + (lane >> 3)] = acc0;
        g_ssrc[(size_t)gw * NH + 4 + (lane >> 3)] = acc1;
    }
}

// ---------------- edge scores: e_val = leaky_relu(s_src[src] + srl_emb.v^T)
__global__ void __launch_bounds__(256) k_eval(const float* __restrict__ srl,
                                              const int* __restrict__ src) {
    __shared__ float sv[NH][FEAT];
    int tid = threadIdx.x;
#pragma unroll
    for (int i = tid; i < NH * FEAT; i += 256)
        ((float*)sv)[i] = g_vfeat[i];
    __syncthreads();

    int warp = tid >> 5, lane = tid & 31;
    int grp = lane >> 3, sl = lane & 7;
    int e = blockIdx.x * 32 + warp * 4 + grp;
    if (e >= NE) return;

    const float4* row = (const float4*)(srl + (size_t)e * FEAT);
    float acc[NH];
#pragma unroll
    for (int h = 0; h < NH; ++h) acc[h] = 0.f;
#pragma unroll
    for (int i = 0; i < 4; ++i) {
        float4 v = row[i * 8 + sl];
        int fb = (i * 8 + sl) * 4;
#pragma unroll
        for (int h = 0; h < NH; ++h) {
            acc[h] += v.x * sv[h][fb + 0];
            acc[h] += v.y * sv[h][fb + 1];
            acc[h] += v.z * sv[h][fb + 2];
            acc[h] += v.w * sv[h][fb + 3];
        }
    }
    float ev = 0.f;
#pragma unroll
    for (int h = 0; h < NH; ++h) {
        float v = acc[h];
        v += __shfl_xor_sync(0xffffffffu, v, 1, 8);
        v += __shfl_xor_sync(0xffffffffu, v, 2, 8);
        v += __shfl_xor_sync(0xffffffffu, v, 4, 8);
        if (h == sl) ev = v;
    }
    int sid = src[e];
    float x = g_ssrc[(size_t)sid * NH + sl] + ev;
    g_eval[(size_t)e * NH + sl] = (x > 0.f) ? x : 0.01f * x;
}

// ---------------- counting sort of edges by dst ----------------------------
__global__ void k_hist(const int* __restrict__ dst) {
    int t = blockIdx.x * blockDim.x + threadIdx.x;
    if (t < NE) atomicAdd(&g_counts[dst[t]], 1);
}

__global__ void __launch_bounds__(1024) k_scan() {
    __shared__ int sh[1024];
    int t = threadIdx.x;
    int base = t * 10;
    int local[10];
    int s = 0;
#pragma unroll
    for (int i = 0; i < 10; ++i) {
        int idx = base + i;
        int c = (idx < NP) ? g_counts[idx] : 0;
        local[i] = s;
        s += c;
    }
    sh[t] = s;
    __syncthreads();
    for (int off = 1; off < 1024; off <<= 1) {
        int v = (t >= off) ? sh[t - off] : 0;
        __syncthreads();
        sh[t] += v;
        __syncthreads();
    }
    int excl = sh[t] - s;
#pragma unroll
    for (int i = 0; i < 10; ++i) {
        int idx = base + i;
        if (idx < NP) {
            int o = excl + local[i];
            g_offsets[idx] = o;
            g_cursor[idx] = o;
        }
    }
}

__global__ void k_scatter(const int* __restrict__ dst) {
    int t = blockIdx.x * blockDim.x + threadIdx.x;
    if (t < NE) {
        int p = atomicAdd(&g_cursor[dst[t]], 1);
        g_edge_sorted[p] = t;
    }
}

// ---------------- per-segment softmax + weighted gather of z ---------------
__global__ void __launch_bounds__(256) k_segment(const int* __restrict__ src,
                                                 float* __restrict__ out) {
    int p = blockIdx.x;
    int t = threadIdx.x;
    int h = t >> 5;
    int start = g_offsets[p];
    int cnt = g_counts[p];
    float* op = out + (size_t)p * HD + t;
    if (cnt == 0) { *op = 0.f; return; }

    float m = -3.0e38f;
    for (int i = 0; i < cnt; ++i) {
        int eid = g_edge_sorted[start + i];
        m = fmaxf(m, g_eval[(size_t)eid * NH + h]);
    }
    float denom = 0.f, acc = 0.f;
    for (int i = 0; i < cnt; ++i) {
        int eid = g_edge_sorted[start + i];
        float w = expf(g_eval[(size_t)eid * NH + h] - m);
        denom += w;
        int sid = src[eid];
        acc += w * g_z[(size_t)sid * HD + t];
    }
    *op = acc / denom;
}

// ---------------- launcher --------------------------------------------------
extern "C" void kernel_launch(void* const* d_in, const int* in_sizes, int n_in,
                              void* d_out, int out_size) {
    const float* h      = (const float*)d_in[0];
    const float* srl    = (const float*)d_in[1];
    const int*   src    = (const int*)d_in[2];
    const int*   dst    = (const int*)d_in[3];
    const float* W_fc   = (const float*)d_in[4];
    const float* W_feat = (const float*)d_in[5];
    const float* W_attn = (const float*)d_in[6];
    float* out = (float*)d_out;

    k_zero_counts<<<(NP + 255) / 256, 256>>>();
    k_vfeat<<<(NH * FEAT + 255) / 256, 256>>>(W_feat, W_attn);

    {
        float* zptr;
        cudaGetSymbolAddress((void**)&zptr, g_z);
        dim3 grid(HD / GBN, (NA + GBM - 1) / GBM);
        k_gemm_3xtf32<<<grid, 256>>>(h, W_fc, zptr);
    }

    k_ssrc<<<(NA * 32 + 255) / 256, 256>>>(W_attn);
    k_eval<<<(NE + 31) / 32, 256>>>(srl, src);

    k_hist<<<(NE + 255) / 256, 256>>>(dst);
    k_scan<<<1, 1024>>>();
    k_scatter<<<(NE + 255) / 256, 256>>>(dst);

    k_segment<<<NP, 256>>>(src, out);
}

// round 4
// speedup vs baseline: 1.6350x; 1.2576x over previous
#include <cuda_runtime.h>
#include <cuda_bf16.h>
#include <cstdint>
#include <math.h>

// Problem constants (fixed by the dataset)
#define NA      50000
#define NP      10000
#define NE      400000
#define IN_DIM  512
#define FEAT    128
#define NH      8
#define OD      32
#define HD      256   // NH*OD

// ---------------- scratch (static device globals; no allocation) -----------
__device__ float g_z[(size_t)NA * HD];        // 51.2 MB
__device__ float g_ssrc[(size_t)NA * NH];     // 1.6 MB
__device__ float g_eval[(size_t)NE * NH];     // 12.8 MB
__device__ float g_vfeat[NH * FEAT];          // 4 KB
__device__ int   g_counts[NP];
__device__ int   g_offsets[NP];
__device__ int   g_cursor[NP];
__device__ int   g_edge_sorted[NE];

// ---------------- small utility kernels ------------------------------------
__global__ void k_zero_counts() {
    int t = blockIdx.x * blockDim.x + threadIdx.x;
    if (t < NP) g_counts[t] = 0;
}

// v[h][f] = sum_d a_feat[d] * W_feat[(h*OD+d)*FEAT + f],  a_feat = W_attn[64..95]
__global__ void k_vfeat(const float* __restrict__ W_feat,
                        const float* __restrict__ W_attn) {
    int t = blockIdx.x * blockDim.x + threadIdx.x;
    if (t >= NH * FEAT) return;
    int h = t / FEAT, f = t % FEAT;
    float acc = 0.f;
#pragma unroll
    for (int d = 0; d < OD; ++d)
        acc += W_attn[2 * OD + d] * W_feat[(size_t)(h * OD + d) * FEAT + f];
    g_vfeat[t] = acc;
}

// ============ 3-term compensated bf16 tensor-core GEMM =====================
// C[M,N] = A[M,K] @ B[N,K]^T  with x = hi(bf16) + lo(bf16):
//   C += Al*Bh + Ah*Bl + Ah*Bh    (Al*Bl ~ 2^-16, dropped)
// Block 128x128x16, warps 2(m)x4(n), warp tile 64x32, mma m16n8k16.
// Splits done ONCE per element at smem-store time; inner loop = LDS + MMA only.
#define GBM 128
#define GBN 128
#define GBK 16
#define KP  (GBK / 2)      // 8 uint32 (bf16x2) per row
#define SPAD 4
#define SSTR (KP + SPAD)   // 12 -> bank-conflict-free fragment loads

#define SIDX(buf, row, kp) ((((buf) * GBM) + (row)) * SSTR + (kp))
#define GEMM_SMEM_BYTES (4 * 2 * GBM * SSTR * 4)   // 49152 = 48KB

__device__ __forceinline__ void bf16_split2(float x, float y,
                                            uint32_t& hi, uint32_t& lo) {
    __nv_bfloat16 hx = __float2bfloat16_rn(x);
    __nv_bfloat16 hy = __float2bfloat16_rn(y);
    float rx = x - __bfloat162float(hx);
    float ry = y - __bfloat162float(hy);
    __nv_bfloat162 hp = __halves2bfloat162(hx, hy);   // low = x
    __nv_bfloat162 lp = __floats2bfloat162_rn(rx, ry);
    hi = *reinterpret_cast<uint32_t*>(&hp);
    lo = *reinterpret_cast<uint32_t*>(&lp);
}

#define MMA_BF16(D, A0, A1, A2, A3, B0, B1)                                   \
    asm volatile(                                                             \
        "mma.sync.aligned.m16n8k16.row.col.f32.bf16.bf16.f32 "                \
        "{%0,%1,%2,%3}, {%4,%5,%6,%7}, {%8,%9}, {%0,%1,%2,%3};"               \
        : "+f"(D[0]), "+f"(D[1]), "+f"(D[2]), "+f"(D[3])                      \
        : "r"(A0), "r"(A1), "r"(A2), "r"(A3), "r"(B0), "r"(B1))

__global__ void __launch_bounds__(256, 2)
k_gemm_bf16x2(const float* __restrict__ A, const float* __restrict__ B,
              float* __restrict__ C) {
    const int M = NA, K = IN_DIM;
    extern __shared__ uint32_t sm[];
    uint32_t* Ah = sm;
    uint32_t* Al = sm + 2 * GBM * SSTR;
    uint32_t* Bh = sm + 4 * GBM * SSTR;
    uint32_t* Bl = sm + 6 * GBM * SSTR;

    const int bm = blockIdx.y * GBM;
    const int bn = blockIdx.x * GBN;
    const int tid = threadIdx.x;
    const int warp = tid >> 5, lane = tid & 31;
    const int g = lane >> 2, tg = lane & 3;
    const int wm = (warp >> 2) * 64;
    const int wn = (warp & 3) * 32;

    float acc[4][4][4];
#pragma unroll
    for (int mi = 0; mi < 4; ++mi)
#pragma unroll
        for (int nj = 0; nj < 4; ++nj)
#pragma unroll
            for (int r = 0; r < 4; ++r) acc[mi][nj][r] = 0.f;

    const int lr = tid >> 2;          // 0..63
    const int lc = (tid & 3) * 4;     // col within 16-float k-chunk
    const int lkp = (tid & 3) * 2;    // uint32 pair index
    const int NITER = K / GBK;        // 32

    float4 ra[2], rb[2];

    // ---- load tile 0 into registers
#pragma unroll
    for (int it = 0; it < 2; ++it) {
        int row = lr + it * 64;
        int grow = bm + row;
        ra[it] = (grow < M) ? *(const float4*)(A + (size_t)grow * K + lc)
                            : make_float4(0.f, 0.f, 0.f, 0.f);
        rb[it] = *(const float4*)(B + (size_t)(bn + row) * K + lc);
    }
    // split + store tile 0
#pragma unroll
    for (int it = 0; it < 2; ++it) {
        int row = lr + it * 64;
        uint32_t h0, l0, h1, l1;
        bf16_split2(ra[it].x, ra[it].y, h0, l0);
        bf16_split2(ra[it].z, ra[it].w, h1, l1);
        Ah[SIDX(0, row, lkp)] = h0; Ah[SIDX(0, row, lkp + 1)] = h1;
        Al[SIDX(0, row, lkp)] = l0; Al[SIDX(0, row, lkp + 1)] = l1;
        bf16_split2(rb[it].x, rb[it].y, h0, l0);
        bf16_split2(rb[it].z, rb[it].w, h1, l1);
        Bh[SIDX(0, row, lkp)] = h0; Bh[SIDX(0, row, lkp + 1)] = h1;
        Bl[SIDX(0, row, lkp)] = l0; Bl[SIDX(0, row, lkp + 1)] = l1;
    }
    __syncthreads();

    for (int t = 0; t < NITER; ++t) {
        // prefetch next tile into registers (in flight during compute)
        if (t + 1 < NITER) {
            int kb = (t + 1) * GBK;
#pragma unroll
            for (int it = 0; it < 2; ++it) {
                int row = lr + it * 64;
                int grow = bm + row;
                ra[it] = (grow < M)
                    ? *(const float4*)(A + (size_t)grow * K + kb + lc)
                    : make_float4(0.f, 0.f, 0.f, 0.f);
                rb[it] = *(const float4*)(B + (size_t)(bn + row) * K + kb + lc);
            }
        }

        // ---- compute on buffer t&1
        const int buf = t & 1;
        uint32_t bhf[4][2], blf[4][2];
#pragma unroll
        for (int nj = 0; nj < 4; ++nj) {
            int row = wn + nj * 8 + g;
            bhf[nj][0] = Bh[SIDX(buf, row, tg)];
            bhf[nj][1] = Bh[SIDX(buf, row, tg + 4)];
            blf[nj][0] = Bl[SIDX(buf, row, tg)];
            blf[nj][1] = Bl[SIDX(buf, row, tg + 4)];
        }
#pragma unroll
        for (int mi = 0; mi < 4; ++mi) {
            int r0 = wm + mi * 16 + g;
            uint32_t ah0 = Ah[SIDX(buf, r0, tg)];
            uint32_t ah1 = Ah[SIDX(buf, r0 + 8, tg)];
            uint32_t ah2 = Ah[SIDX(buf, r0, tg + 4)];
            uint32_t ah3 = Ah[SIDX(buf, r0 + 8, tg + 4)];
            uint32_t al0 = Al[SIDX(buf, r0, tg)];
            uint32_t al1 = Al[SIDX(buf, r0 + 8, tg)];
            uint32_t al2 = Al[SIDX(buf, r0, tg + 4)];
            uint32_t al3 = Al[SIDX(buf, r0 + 8, tg + 4)];
#pragma unroll
            for (int nj = 0; nj < 4; ++nj) {
                MMA_BF16(acc[mi][nj], al0, al1, al2, al3, bhf[nj][0], bhf[nj][1]);
                MMA_BF16(acc[mi][nj], ah0, ah1, ah2, ah3, blf[nj][0], blf[nj][1]);
                MMA_BF16(acc[mi][nj], ah0, ah1, ah2, ah3, bhf[nj][0], bhf[nj][1]);
            }
        }

        // ---- split + store next tile, then sync
        if (t + 1 < NITER) {
            const int nb = (t + 1) & 1;
#pragma unroll
            for (int it = 0; it < 2; ++it) {
                int row = lr + it * 64;
                uint32_t h0, l0, h1, l1;
                bf16_split2(ra[it].x, ra[it].y, h0, l0);
                bf16_split2(ra[it].z, ra[it].w, h1, l1);
                Ah[SIDX(nb, row, lkp)] = h0; Ah[SIDX(nb, row, lkp + 1)] = h1;
                Al[SIDX(nb, row, lkp)] = l0; Al[SIDX(nb, row, lkp + 1)] = l1;
                bf16_split2(rb[it].x, rb[it].y, h0, l0);
                bf16_split2(rb[it].z, rb[it].w, h1, l1);
                Bh[SIDX(nb, row, lkp)] = h0; Bh[SIDX(nb, row, lkp + 1)] = h1;
                Bl[SIDX(nb, row, lkp)] = l0; Bl[SIDX(nb, row, lkp + 1)] = l1;
            }
            __syncthreads();
        }
    }

    // ---- epilogue
#pragma unroll
    for (int mi = 0; mi < 4; ++mi) {
        int row0 = bm + wm + mi * 16 + g;
#pragma unroll
        for (int nj = 0; nj < 4; ++nj) {
            int col = bn + wn + nj * 8 + tg * 2;
            if (row0 < M)
                *(float2*)&C[(size_t)row0 * HD + col] =
                    make_float2(acc[mi][nj][0], acc[mi][nj][1]);
            if (row0 + 8 < M)
                *(float2*)&C[(size_t)(row0 + 8) * HD + col] =
                    make_float2(acc[mi][nj][2], acc[mi][nj][3]);
        }
    }
}

// ---------------- s_src[n,h] = z[n,h,:] . a_src  (warp per node, coalesced) --
__global__ void __launch_bounds__(256) k_ssrc(const float* __restrict__ W_attn) {
    int gw = (blockIdx.x * blockDim.x + threadIdx.x) >> 5;
    int lane = threadIdx.x & 31;
    if (gw >= NA) return;
    const float4* zp = (const float4*)(g_z + (size_t)gw * HD);
    float4 v0 = zp[lane];
    float4 v1 = zp[lane + 32];
    float4 a4 = *(const float4*)(W_attn + (lane & 7) * 4);
    float acc0 = v0.x * a4.x + v0.y * a4.y + v0.z * a4.z + v0.w * a4.w;
    float acc1 = v1.x * a4.x + v1.y * a4.y + v1.z * a4.z + v1.w * a4.w;
#pragma unroll
    for (int off = 1; off < 8; off <<= 1) {
        acc0 += __shfl_xor_sync(0xffffffffu, acc0, off);
        acc1 += __shfl_xor_sync(0xffffffffu, acc1, off);
    }
    if ((lane & 7) == 0) {
        g_ssrc[(size_t)gw * NH + (lane >> 3)] = acc0;
        g_ssrc[(size_t)gw * NH + 4 + (lane >> 3)] = acc1;
    }
}

// ---------------- edge scores: e_val = leaky_relu(s_src[src] + srl_emb.v^T)
__global__ void __launch_bounds__(256) k_eval(const float* __restrict__ srl,
                                              const int* __restrict__ src) {
    __shared__ float sv[NH][FEAT];
    int tid = threadIdx.x;
#pragma unroll
    for (int i = tid; i < NH * FEAT; i += 256)
        ((float*)sv)[i] = g_vfeat[i];
    __syncthreads();

    int warp = tid >> 5, lane = tid & 31;
    int grp = lane >> 3, sl = lane & 7;
    int e = blockIdx.x * 32 + warp * 4 + grp;
    if (e >= NE) return;

    const float4* row = (const float4*)(srl + (size_t)e * FEAT);
    float acc[NH];
#pragma unroll
    for (int h = 0; h < NH; ++h) acc[h] = 0.f;
#pragma unroll
    for (int i = 0; i < 4; ++i) {
        float4 v = row[i * 8 + sl];
        int fb = (i * 8 + sl) * 4;
#pragma unroll
        for (int h = 0; h < NH; ++h) {
            acc[h] += v.x * sv[h][fb + 0];
            acc[h] += v.y * sv[h][fb + 1];
            acc[h] += v.z * sv[h][fb + 2];
            acc[h] += v.w * sv[h][fb + 3];
        }
    }
    float ev = 0.f;
#pragma unroll
    for (int h = 0; h < NH; ++h) {
        float v = acc[h];
        v += __shfl_xor_sync(0xffffffffu, v, 1, 8);
        v += __shfl_xor_sync(0xffffffffu, v, 2, 8);
        v += __shfl_xor_sync(0xffffffffu, v, 4, 8);
        if (h == sl) ev = v;
    }
    int sid = src[e];
    float x = g_ssrc[(size_t)sid * NH + sl] + ev;
    g_eval[(size_t)e * NH + sl] = (x > 0.f) ? x : 0.01f * x;
}

// ---------------- counting sort of edges by dst ----------------------------
__global__ void k_hist(const int* __restrict__ dst) {
    int t = blockIdx.x * blockDim.x + threadIdx.x;
    if (t < NE) atomicAdd(&g_counts[dst[t]], 1);
}

__global__ void __launch_bounds__(1024) k_scan() {
    __shared__ int sh[1024];
    int t = threadIdx.x;
    int base = t * 10;
    int local[10];
    int s = 0;
#pragma unroll
    for (int i = 0; i < 10; ++i) {
        int idx = base + i;
        int c = (idx < NP) ? g_counts[idx] : 0;
        local[i] = s;
        s += c;
    }
    sh[t] = s;
    __syncthreads();
    for (int off = 1; off < 1024; off <<= 1) {
        int v = (t >= off) ? sh[t - off] : 0;
        __syncthreads();
        sh[t] += v;
        __syncthreads();
    }
    int excl = sh[t] - s;
#pragma unroll
    for (int i = 0; i < 10; ++i) {
        int idx = base + i;
        if (idx < NP) {
            int o = excl + local[i];
            g_offsets[idx] = o;
            g_cursor[idx] = o;
        }
    }
}

__global__ void k_scatter(const int* __restrict__ dst) {
    int t = blockIdx.x * blockDim.x + threadIdx.x;
    if (t < NE) {
        int p = atomicAdd(&g_cursor[dst[t]], 1);
        g_edge_sorted[p] = t;
    }
}

// ---------------- per-segment softmax + weighted gather of z ---------------
__global__ void __launch_bounds__(256) k_segment(const int* __restrict__ src,
                                                 float* __restrict__ out) {
    int p = blockIdx.x;
    int t = threadIdx.x;
    int h = t >> 5;
    int start = g_offsets[p];
    int cnt = g_counts[p];
    float* op = out + (size_t)p * HD + t;
    if (cnt == 0) { *op = 0.f; return; }

    float m = -3.0e38f;
    for (int i = 0; i < cnt; ++i) {
        int eid = g_edge_sorted[start + i];
        m = fmaxf(m, g_eval[(size_t)eid * NH + h]);
    }
    float denom = 0.f, acc = 0.f;
    for (int i = 0; i < cnt; ++i) {
        int eid = g_edge_sorted[start + i];
        float w = expf(g_eval[(size_t)eid * NH + h] - m);
        denom += w;
        int sid = src[eid];
        acc += w * g_z[(size_t)sid * HD + t];
    }
    *op = acc / denom;
}

// ---------------- launcher --------------------------------------------------
extern "C" void kernel_launch(void* const* d_in, const int* in_sizes, int n_in,
                              void* d_out, int out_size) {
    const float* h      = (const float*)d_in[0];
    const float* srl    = (const float*)d_in[1];
    const int*   src    = (const int*)d_in[2];
    const int*   dst    = (const int*)d_in[3];
    const float* W_fc   = (const float*)d_in[4];
    const float* W_feat = (const float*)d_in[5];
    const float* W_attn = (const float*)d_in[6];
    float* out = (float*)d_out;

    k_zero_counts<<<(NP + 255) / 256, 256>>>();
    k_vfeat<<<(NH * FEAT + 255) / 256, 256>>>(W_feat, W_attn);

    {
        float* zptr;
        cudaGetSymbolAddress((void**)&zptr, g_z);
        dim3 grid(HD / GBN, (NA + GBM - 1) / GBM);
        k_gemm_bf16x2<<<grid, 256, GEMM_SMEM_BYTES>>>(h, W_fc, zptr);
    }

    k_ssrc<<<(NA * 32 + 255) / 256, 256>>>(W_attn);
    k_eval<<<(NE + 31) / 32, 256>>>(srl, src);

    k_hist<<<(NE + 255) / 256, 256>>>(dst);
    k_scan<<<1, 1024>>>();
    k_scatter<<<(NE + 255) / 256, 256>>>(dst);

    k_segment<<<NP, 256>>>(src, out);
}